// round 1
// baseline (speedup 1.0000x reference)
#include <cuda_runtime.h>
#include <cstdint>

// Problem constants (fixed shapes)
#define Bb 4
#define Cc 256
#define C2v 128
#define Nn 4096

// Scratch (allocation-free rule: __device__ globals)
__device__ float g_q[(size_t)Bb * Nn * C2v];          // [B, N, 128] q^T
__device__ float g_k[(size_t)Bb * Nn * C2v];          // [B, N, 128] masked k^T
__device__ float g_v[(size_t)Bb * Nn * Cc];           // [B, N, 256] v^T
__device__ float g_att[(size_t)Bb * Nn * Nn];         // [B, N, N] energy / attention

// GEMM tiling
#define BM 128
#define BN 128
#define BK 8
#define TM 8
#define TN 8
#define SSTR 132   // padded smem row stride (conflict-free transposed stores)

// ---------------------------------------------------------------------------
// Fast exp: exp(x) = 2^(x*log2e), degree-5 poly for 2^f on [0,1), exponent via
// int bit construction. x <= 0 (post max-subtract); clamp at 2^-126.
// ---------------------------------------------------------------------------
__device__ __forceinline__ float fexp(float x) {
    float t = fmaxf(x * 1.4426950408889634f, -126.0f);
    float fi = floorf(t);
    float f = t - fi;
    float p = 0.0013333558f;
    p = fmaf(p, f, 0.0096181291f);
    p = fmaf(p, f, 0.0555041087f);
    p = fmaf(p, f, 0.2402265069f);
    p = fmaf(p, f, 0.6931471806f);
    p = fmaf(p, f, 1.0f);
    float s = __int_as_float(((int)fi + 127) << 23);
    return p * s;
}

// ---------------------------------------------------------------------------
// Kernel 1: projections.  For each batch b:
//   qT[b,n,i] = sum_c x[b,c,n] Wq[i,c] + bq[i]
//   kT[b,n,i] = (sum_c x[b,c,n] Wk[i,c] + bk[i]) * (1-mask) * skin
//   vT[b,n,j] = sum_c x[b,c,n] Wv[j,c] + bv[j]
// GEMM: M=N(pixels)=4096, Nout=512 (128 q | 128 k | 256 v), K=256.
// grid (4, 32, B). blockIdx.x selects which weight matrix slice.
// ---------------------------------------------------------------------------
__global__ __launch_bounds__(256) void proj_kernel(
    const float* __restrict__ x, const float* __restrict__ mask,
    const float* __restrict__ skin,
    const float* __restrict__ Wq, const float* __restrict__ bq,
    const float* __restrict__ Wk, const float* __restrict__ bk,
    const float* __restrict__ Wv, const float* __restrict__ bv)
{
    __shared__ float As[BK * SSTR];
    __shared__ float Bs[BK * SSTR];

    const int b   = blockIdx.z;
    const int m0  = blockIdx.y * BM;
    const int oblk = blockIdx.x;   // 0:q, 1:k, 2:v[0:128), 3:v[128:256)

    const float* Wp; const float* biasp; int orow0;
    if (oblk == 0)      { Wp = Wq; biasp = bq; orow0 = 0; }
    else if (oblk == 1) { Wp = Wk; biasp = bk; orow0 = 0; }
    else                { Wp = Wv; biasp = bv; orow0 = (oblk - 2) * 128; }

    const int tid = threadIdx.x;
    const int tx = tid & 15, ty = tid >> 4;
    const float* xb = x + (size_t)b * Cc * Nn;

    // loader indices
    const int a_k = tid >> 5;            // 0..7
    const int a_m = (tid & 31) * 4;      // 0..124
    const int b_o = tid >> 1;            // 0..127
    const int b_kg = (tid & 1) * 4;      // 0 or 4

    float acc[TM][TN] = {};

    for (int k0 = 0; k0 < Cc; k0 += BK) {
        // As[k][m] = x[b][k0+k][m0+m]  (direct, coalesced over m)
        float4 av = *reinterpret_cast<const float4*>(
            xb + (size_t)(k0 + a_k) * Nn + m0 + a_m);
        *reinterpret_cast<float4*>(&As[a_k * SSTR + a_m]) = av;
        // Bs[k][o] = Wp[orow0+o][k0+k]  (transposed store)
        float4 wv = *reinterpret_cast<const float4*>(
            Wp + (size_t)(orow0 + b_o) * Cc + k0 + b_kg);
        Bs[(b_kg + 0) * SSTR + b_o] = wv.x;
        Bs[(b_kg + 1) * SSTR + b_o] = wv.y;
        Bs[(b_kg + 2) * SSTR + b_o] = wv.z;
        Bs[(b_kg + 3) * SSTR + b_o] = wv.w;
        __syncthreads();
        #pragma unroll
        for (int k = 0; k < BK; k++) {
            float4 a0 = *reinterpret_cast<const float4*>(&As[k * SSTR + ty * TM]);
            float4 a1 = *reinterpret_cast<const float4*>(&As[k * SSTR + ty * TM + 4]);
            float4 b0 = *reinterpret_cast<const float4*>(&Bs[k * SSTR + tx * TN]);
            float4 b1 = *reinterpret_cast<const float4*>(&Bs[k * SSTR + tx * TN + 4]);
            float a[TM] = {a0.x, a0.y, a0.z, a0.w, a1.x, a1.y, a1.z, a1.w};
            float bb[TN] = {b0.x, b0.y, b0.z, b0.w, b1.x, b1.y, b1.z, b1.w};
            #pragma unroll
            for (int i = 0; i < TM; i++)
                #pragma unroll
                for (int j = 0; j < TN; j++)
                    acc[i][j] = fmaf(a[i], bb[j], acc[i][j]);
        }
        __syncthreads();
    }

    const int obase = tx * TN;
    float bias[TN];
    #pragma unroll
    for (int j = 0; j < TN; j++) bias[j] = biasp[orow0 + obase + j];

    #pragma unroll
    for (int i = 0; i < TM; i++) {
        const int m = m0 + ty * TM + i;
        float r[TN];
        #pragma unroll
        for (int j = 0; j < TN; j++) r[j] = acc[i][j] + bias[j];
        if (oblk == 0) {
            float* dst = g_q + ((size_t)b * Nn + m) * C2v + obase;
            *reinterpret_cast<float4*>(dst)     = make_float4(r[0], r[1], r[2], r[3]);
            *reinterpret_cast<float4*>(dst + 4) = make_float4(r[4], r[5], r[6], r[7]);
        } else if (oblk == 1) {
            const float f = (1.0f - mask[b * Nn + m]) * skin[b * Nn + m];
            float* dst = g_k + ((size_t)b * Nn + m) * C2v + obase;
            *reinterpret_cast<float4*>(dst)     = make_float4(r[0]*f, r[1]*f, r[2]*f, r[3]*f);
            *reinterpret_cast<float4*>(dst + 4) = make_float4(r[4]*f, r[5]*f, r[6]*f, r[7]*f);
        } else {
            float* dst = g_v + ((size_t)b * Nn + m) * Cc + orow0 + obase;
            *reinterpret_cast<float4*>(dst)     = make_float4(r[0], r[1], r[2], r[3]);
            *reinterpret_cast<float4*>(dst + 4) = make_float4(r[4], r[5], r[6], r[7]);
        }
    }
}

// ---------------------------------------------------------------------------
// Kernel 2: energy S[b,m,n] = sum_k qT[b,m,k] * kT[b,n,k]
// GEMM per batch: M=4096, N=4096, K=128. grid (32, 32, B).
// ---------------------------------------------------------------------------
__global__ __launch_bounds__(256) void score_kernel()
{
    __shared__ float As[BK * SSTR];
    __shared__ float Bs[BK * SSTR];

    const int b  = blockIdx.z;
    const int m0 = blockIdx.y * BM;
    const int n0 = blockIdx.x * BN;
    const int tid = threadIdx.x;
    const int tx = tid & 15, ty = tid >> 4;

    const float* Aq = g_q + (size_t)b * Nn * C2v;
    const float* Bk = g_k + (size_t)b * Nn * C2v;

    // both tiles are transposed loads: row = tid>>1 (0..127), kg = (tid&1)*4
    const int r_m = tid >> 1;
    const int r_kg = (tid & 1) * 4;

    float acc[TM][TN] = {};

    for (int k0 = 0; k0 < C2v; k0 += BK) {
        float4 av = *reinterpret_cast<const float4*>(
            Aq + (size_t)(m0 + r_m) * C2v + k0 + r_kg);
        As[(r_kg + 0) * SSTR + r_m] = av.x;
        As[(r_kg + 1) * SSTR + r_m] = av.y;
        As[(r_kg + 2) * SSTR + r_m] = av.z;
        As[(r_kg + 3) * SSTR + r_m] = av.w;
        float4 kv = *reinterpret_cast<const float4*>(
            Bk + (size_t)(n0 + r_m) * C2v + k0 + r_kg);
        Bs[(r_kg + 0) * SSTR + r_m] = kv.x;
        Bs[(r_kg + 1) * SSTR + r_m] = kv.y;
        Bs[(r_kg + 2) * SSTR + r_m] = kv.z;
        Bs[(r_kg + 3) * SSTR + r_m] = kv.w;
        __syncthreads();
        #pragma unroll
        for (int k = 0; k < BK; k++) {
            float4 a0 = *reinterpret_cast<const float4*>(&As[k * SSTR + ty * TM]);
            float4 a1 = *reinterpret_cast<const float4*>(&As[k * SSTR + ty * TM + 4]);
            float4 b0 = *reinterpret_cast<const float4*>(&Bs[k * SSTR + tx * TN]);
            float4 b1 = *reinterpret_cast<const float4*>(&Bs[k * SSTR + tx * TN + 4]);
            float a[TM] = {a0.x, a0.y, a0.z, a0.w, a1.x, a1.y, a1.z, a1.w};
            float bb[TN] = {b0.x, b0.y, b0.z, b0.w, b1.x, b1.y, b1.z, b1.w};
            #pragma unroll
            for (int i = 0; i < TM; i++)
                #pragma unroll
                for (int j = 0; j < TN; j++)
                    acc[i][j] = fmaf(a[i], bb[j], acc[i][j]);
        }
        __syncthreads();
    }

    #pragma unroll
    for (int i = 0; i < TM; i++) {
        const size_t m = (size_t)(m0 + ty * TM + i);
        float* dst = g_att + ((size_t)b * Nn + m) * Nn + n0 + tx * TN;
        *reinterpret_cast<float4*>(dst)     = make_float4(acc[i][0], acc[i][1], acc[i][2], acc[i][3]);
        *reinterpret_cast<float4*>(dst + 4) = make_float4(acc[i][4], acc[i][5], acc[i][6], acc[i][7]);
    }
}

// ---------------------------------------------------------------------------
// Kernel 3: row softmax over g_att rows (length 4096). One block per row.
// Row values held in registers (16/thread); FFMA-poly exp (no MUFU storm).
// ---------------------------------------------------------------------------
__global__ __launch_bounds__(256) void softmax_kernel()
{
    const size_t row = blockIdx.x;                // 0 .. B*N-1
    float* p = g_att + row * (size_t)Nn;
    const int t = threadIdx.x;

    float v[16];
    float mx = -1e30f;
    #pragma unroll
    for (int i = 0; i < 16; i++) {
        v[i] = p[t + i * 256];
        mx = fmaxf(mx, v[i]);
    }
    #pragma unroll
    for (int o = 16; o; o >>= 1) mx = fmaxf(mx, __shfl_xor_sync(0xffffffffu, mx, o));

    __shared__ float red[8];
    __shared__ float bmax, binv;
    if ((t & 31) == 0) red[t >> 5] = mx;
    __syncthreads();
    if (t == 0) {
        float m2 = red[0];
        #pragma unroll
        for (int w = 1; w < 8; w++) m2 = fmaxf(m2, red[w]);
        bmax = m2;
    }
    __syncthreads();
    mx = bmax;

    float s = 0.0f;
    #pragma unroll
    for (int i = 0; i < 16; i++) { v[i] = fexp(v[i] - mx); s += v[i]; }
    #pragma unroll
    for (int o = 16; o; o >>= 1) s += __shfl_xor_sync(0xffffffffu, s, o);
    if ((t & 31) == 0) red[t >> 5] = s;
    __syncthreads();
    if (t == 0) {
        float s2 = 0.0f;
        #pragma unroll
        for (int w = 0; w < 8; w++) s2 += red[w];
        binv = 1.0f / s2;
    }
    __syncthreads();
    const float inv = binv;
    #pragma unroll
    for (int i = 0; i < 16; i++) p[t + i * 256] = v[i] * inv;
}

// ---------------------------------------------------------------------------
// Kernel 4: out[b,c,m] = gamma * (sum_n A[b,m,n] vT[b,n,c]) * mask*skin + x
// Computed as outT tile [c rows x m cols] so final stores are m-contiguous.
// M=Cc=256 (c), N=4096 (m), K=4096 (n). grid (2, 32, B).
// ---------------------------------------------------------------------------
__global__ __launch_bounds__(256) void av_kernel(
    const float* __restrict__ x, const float* __restrict__ mask,
    const float* __restrict__ skin, const float* __restrict__ gamma,
    float* __restrict__ out)
{
    __shared__ float As[BK * SSTR];
    __shared__ float Bs[BK * SSTR];

    const int b  = blockIdx.z;
    const int c0 = blockIdx.x * BM;
    const int m0 = blockIdx.y * BN;
    const int tid = threadIdx.x;
    const int tx = tid & 15, ty = tid >> 4;

    const float* Vb = g_v + (size_t)b * Nn * Cc;
    const float* Ab = g_att + (size_t)b * Nn * Nn;

    const int va_n = tid >> 5;           // 0..7
    const int va_c = (tid & 31) * 4;     // 0..124
    const int bt_m = tid >> 1;           // 0..127
    const int bt_ng = (tid & 1) * 4;     // 0 or 4

    float acc[TM][TN] = {};

    for (int k0 = 0; k0 < Nn; k0 += BK) {
        // As[n][c] = vT[k0+n][c0+c]  (direct)
        float4 av = *reinterpret_cast<const float4*>(
            Vb + (size_t)(k0 + va_n) * Cc + c0 + va_c);
        *reinterpret_cast<float4*>(&As[va_n * SSTR + va_c]) = av;
        // Bs[n][m] = att[m0+m][k0+n]  (transposed)
        float4 tv = *reinterpret_cast<const float4*>(
            Ab + (size_t)(m0 + bt_m) * Nn + k0 + bt_ng);
        Bs[(bt_ng + 0) * SSTR + bt_m] = tv.x;
        Bs[(bt_ng + 1) * SSTR + bt_m] = tv.y;
        Bs[(bt_ng + 2) * SSTR + bt_m] = tv.z;
        Bs[(bt_ng + 3) * SSTR + bt_m] = tv.w;
        __syncthreads();
        #pragma unroll
        for (int k = 0; k < BK; k++) {
            float4 a0 = *reinterpret_cast<const float4*>(&As[k * SSTR + ty * TM]);
            float4 a1 = *reinterpret_cast<const float4*>(&As[k * SSTR + ty * TM + 4]);
            float4 b0 = *reinterpret_cast<const float4*>(&Bs[k * SSTR + tx * TN]);
            float4 b1 = *reinterpret_cast<const float4*>(&Bs[k * SSTR + tx * TN + 4]);
            float a[TM] = {a0.x, a0.y, a0.z, a0.w, a1.x, a1.y, a1.z, a1.w};
            float bb[TN] = {b0.x, b0.y, b0.z, b0.w, b1.x, b1.y, b1.z, b1.w};
            #pragma unroll
            for (int i = 0; i < TM; i++)
                #pragma unroll
                for (int j = 0; j < TN; j++)
                    acc[i][j] = fmaf(a[i], bb[j], acc[i][j]);
        }
        __syncthreads();
    }

    const float g = *gamma;
    const int mb = m0 + tx * TN;
    float fm[TN];
    {
        float4 mk0 = *reinterpret_cast<const float4*>(mask + (size_t)b * Nn + mb);
        float4 mk1 = *reinterpret_cast<const float4*>(mask + (size_t)b * Nn + mb + 4);
        float4 sk0 = *reinterpret_cast<const float4*>(skin + (size_t)b * Nn + mb);
        float4 sk1 = *reinterpret_cast<const float4*>(skin + (size_t)b * Nn + mb + 4);
        fm[0] = mk0.x * sk0.x; fm[1] = mk0.y * sk0.y;
        fm[2] = mk0.z * sk0.z; fm[3] = mk0.w * sk0.w;
        fm[4] = mk1.x * sk1.x; fm[5] = mk1.y * sk1.y;
        fm[6] = mk1.z * sk1.z; fm[7] = mk1.w * sk1.w;
    }

    #pragma unroll
    for (int i = 0; i < TM; i++) {
        const int c = c0 + ty * TM + i;
        const size_t base = (size_t)b * Cc * Nn + (size_t)c * Nn + mb;
        float4 x0 = *reinterpret_cast<const float4*>(x + base);
        float4 x1 = *reinterpret_cast<const float4*>(x + base + 4);
        float4 r0, r1;
        r0.x = fmaf(g, acc[i][0] * fm[0], x0.x);
        r0.y = fmaf(g, acc[i][1] * fm[1], x0.y);
        r0.z = fmaf(g, acc[i][2] * fm[2], x0.z);
        r0.w = fmaf(g, acc[i][3] * fm[3], x0.w);
        r1.x = fmaf(g, acc[i][4] * fm[4], x1.x);
        r1.y = fmaf(g, acc[i][5] * fm[5], x1.y);
        r1.z = fmaf(g, acc[i][6] * fm[6], x1.z);
        r1.w = fmaf(g, acc[i][7] * fm[7], x1.w);
        *reinterpret_cast<float4*>(out + base)     = r0;
        *reinterpret_cast<float4*>(out + base + 4) = r1;
    }
}

// ---------------------------------------------------------------------------
extern "C" void kernel_launch(void* const* d_in, const int* in_sizes, int n_in,
                              void* d_out, int out_size)
{
    (void)in_sizes; (void)n_in; (void)out_size;
    const float* x     = (const float*)d_in[0];
    const float* mask  = (const float*)d_in[1];
    const float* skin  = (const float*)d_in[2];
    const float* Wq    = (const float*)d_in[3];
    const float* bq    = (const float*)d_in[4];
    const float* Wk    = (const float*)d_in[5];
    const float* bk    = (const float*)d_in[6];
    const float* Wv    = (const float*)d_in[7];
    const float* bv    = (const float*)d_in[8];
    const float* gamma = (const float*)d_in[9];
    float* out = (float*)d_out;

    dim3 gA(4, 32, Bb);
    proj_kernel<<<gA, 256>>>(x, mask, skin, Wq, bq, Wk, bk, Wv, bv);

    dim3 gB(32, 32, Bb);
    score_kernel<<<gB, 256>>>();

    softmax_kernel<<<Bb * Nn, 256>>>();

    dim3 gD(2, 32, Bb);
    av_kernel<<<gD, 256>>>(x, mask, skin, gamma, out);
}

// round 2
// speedup vs baseline: 1.0028x; 1.0028x over previous
#include <cuda_runtime.h>
#include <cstdint>

// Problem constants (fixed shapes)
#define Bb 4
#define Cc 256
#define C2v 128
#define Nn 4096

// Scratch (allocation-free rule: __device__ globals)
__device__ float g_q[(size_t)Bb * Nn * C2v];          // [B, N, 128] q^T
__device__ float g_k[(size_t)Bb * Nn * C2v];          // [B, N, 128] masked k^T
__device__ float g_v[(size_t)Bb * Nn * Cc];           // [B, N, 256] v^T
__device__ float g_att[(size_t)Bb * Nn * Nn];         // [B, N, N] energy / attention

// GEMM tiling
#define BM 128
#define BN 128
#define BK 8
#define TM 8
#define TN 8
#define SSTR 132   // padded smem row stride (conflict-free transposed stores)

// ---------------------------------------------------------------------------
// Fast exp: exp(x) = 2^(x*log2e), degree-5 poly for 2^f on [0,1), exponent via
// int bit construction. x <= 0 (post max-subtract); clamp at 2^-126.
// ---------------------------------------------------------------------------
__device__ __forceinline__ float fexp(float x) {
    float t = fmaxf(x * 1.4426950408889634f, -126.0f);
    float fi = floorf(t);
    float f = t - fi;
    float p = 0.0013333558f;
    p = fmaf(p, f, 0.0096181291f);
    p = fmaf(p, f, 0.0555041087f);
    p = fmaf(p, f, 0.2402265069f);
    p = fmaf(p, f, 0.6931471806f);
    p = fmaf(p, f, 1.0f);
    float s = __int_as_float(((int)fi + 127) << 23);
    return p * s;
}

// ---------------------------------------------------------------------------
// Kernel 1: projections.  For each batch b:
//   qT[b,n,i] = sum_c x[b,c,n] Wq[i,c] + bq[i]
//   kT[b,n,i] = (sum_c x[b,c,n] Wk[i,c] + bk[i]) * (1-mask) * skin
//   vT[b,n,j] = sum_c x[b,c,n] Wv[j,c] + bv[j]
// GEMM: M=N(pixels)=4096, Nout=512 (128 q | 128 k | 256 v), K=256.
// grid (4, 32, B). blockIdx.x selects which weight matrix slice.
// ---------------------------------------------------------------------------
__global__ __launch_bounds__(256) void proj_kernel(
    const float* __restrict__ x, const float* __restrict__ mask,
    const float* __restrict__ skin,
    const float* __restrict__ Wq, const float* __restrict__ bq,
    const float* __restrict__ Wk, const float* __restrict__ bk,
    const float* __restrict__ Wv, const float* __restrict__ bv)
{
    __shared__ float As[BK * SSTR];
    __shared__ float Bs[BK * SSTR];

    const int b   = blockIdx.z;
    const int m0  = blockIdx.y * BM;
    const int oblk = blockIdx.x;   // 0:q, 1:k, 2:v[0:128), 3:v[128:256)

    const float* Wp; const float* biasp; int orow0;
    if (oblk == 0)      { Wp = Wq; biasp = bq; orow0 = 0; }
    else if (oblk == 1) { Wp = Wk; biasp = bk; orow0 = 0; }
    else                { Wp = Wv; biasp = bv; orow0 = (oblk - 2) * 128; }

    const int tid = threadIdx.x;
    const int tx = tid & 15, ty = tid >> 4;
    const float* xb = x + (size_t)b * Cc * Nn;

    // loader indices
    const int a_k = tid >> 5;            // 0..7
    const int a_m = (tid & 31) * 4;      // 0..124
    const int b_o = tid >> 1;            // 0..127
    const int b_kg = (tid & 1) * 4;      // 0 or 4

    float acc[TM][TN] = {};

    for (int k0 = 0; k0 < Cc; k0 += BK) {
        // As[k][m] = x[b][k0+k][m0+m]  (direct, coalesced over m)
        float4 av = *reinterpret_cast<const float4*>(
            xb + (size_t)(k0 + a_k) * Nn + m0 + a_m);
        *reinterpret_cast<float4*>(&As[a_k * SSTR + a_m]) = av;
        // Bs[k][o] = Wp[orow0+o][k0+k]  (transposed store)
        float4 wv = *reinterpret_cast<const float4*>(
            Wp + (size_t)(orow0 + b_o) * Cc + k0 + b_kg);
        Bs[(b_kg + 0) * SSTR + b_o] = wv.x;
        Bs[(b_kg + 1) * SSTR + b_o] = wv.y;
        Bs[(b_kg + 2) * SSTR + b_o] = wv.z;
        Bs[(b_kg + 3) * SSTR + b_o] = wv.w;
        __syncthreads();
        #pragma unroll
        for (int k = 0; k < BK; k++) {
            float4 a0 = *reinterpret_cast<const float4*>(&As[k * SSTR + ty * TM]);
            float4 a1 = *reinterpret_cast<const float4*>(&As[k * SSTR + ty * TM + 4]);
            float4 b0 = *reinterpret_cast<const float4*>(&Bs[k * SSTR + tx * TN]);
            float4 b1 = *reinterpret_cast<const float4*>(&Bs[k * SSTR + tx * TN + 4]);
            float a[TM] = {a0.x, a0.y, a0.z, a0.w, a1.x, a1.y, a1.z, a1.w};
            float bb[TN] = {b0.x, b0.y, b0.z, b0.w, b1.x, b1.y, b1.z, b1.w};
            #pragma unroll
            for (int i = 0; i < TM; i++)
                #pragma unroll
                for (int j = 0; j < TN; j++)
                    acc[i][j] = fmaf(a[i], bb[j], acc[i][j]);
        }
        __syncthreads();
    }

    const int obase = tx * TN;
    float bias[TN];
    #pragma unroll
    for (int j = 0; j < TN; j++) bias[j] = biasp[orow0 + obase + j];

    #pragma unroll
    for (int i = 0; i < TM; i++) {
        const int m = m0 + ty * TM + i;
        float r[TN];
        #pragma unroll
        for (int j = 0; j < TN; j++) r[j] = acc[i][j] + bias[j];
        if (oblk == 0) {
            float* dst = g_q + ((size_t)b * Nn + m) * C2v + obase;
            *reinterpret_cast<float4*>(dst)     = make_float4(r[0], r[1], r[2], r[3]);
            *reinterpret_cast<float4*>(dst + 4) = make_float4(r[4], r[5], r[6], r[7]);
        } else if (oblk == 1) {
            const float f = (1.0f - mask[b * Nn + m]) * skin[b * Nn + m];
            float* dst = g_k + ((size_t)b * Nn + m) * C2v + obase;
            *reinterpret_cast<float4*>(dst)     = make_float4(r[0]*f, r[1]*f, r[2]*f, r[3]*f);
            *reinterpret_cast<float4*>(dst + 4) = make_float4(r[4]*f, r[5]*f, r[6]*f, r[7]*f);
        } else {
            float* dst = g_v + ((size_t)b * Nn + m) * Cc + orow0 + obase;
            *reinterpret_cast<float4*>(dst)     = make_float4(r[0], r[1], r[2], r[3]);
            *reinterpret_cast<float4*>(dst + 4) = make_float4(r[4], r[5], r[6], r[7]);
        }
    }
}

// ---------------------------------------------------------------------------
// Kernel 2: energy S[b,m,n] = sum_k qT[b,m,k] * kT[b,n,k]
// GEMM per batch: M=4096, N=4096, K=128. grid (32, 32, B).
// ---------------------------------------------------------------------------
__global__ __launch_bounds__(256) void score_kernel()
{
    __shared__ float As[BK * SSTR];
    __shared__ float Bs[BK * SSTR];

    const int b  = blockIdx.z;
    const int m0 = blockIdx.y * BM;
    const int n0 = blockIdx.x * BN;
    const int tid = threadIdx.x;
    const int tx = tid & 15, ty = tid >> 4;

    const float* Aq = g_q + (size_t)b * Nn * C2v;
    const float* Bk = g_k + (size_t)b * Nn * C2v;

    // both tiles are transposed loads: row = tid>>1 (0..127), kg = (tid&1)*4
    const int r_m = tid >> 1;
    const int r_kg = (tid & 1) * 4;

    float acc[TM][TN] = {};

    for (int k0 = 0; k0 < C2v; k0 += BK) {
        float4 av = *reinterpret_cast<const float4*>(
            Aq + (size_t)(m0 + r_m) * C2v + k0 + r_kg);
        As[(r_kg + 0) * SSTR + r_m] = av.x;
        As[(r_kg + 1) * SSTR + r_m] = av.y;
        As[(r_kg + 2) * SSTR + r_m] = av.z;
        As[(r_kg + 3) * SSTR + r_m] = av.w;
        float4 kv = *reinterpret_cast<const float4*>(
            Bk + (size_t)(n0 + r_m) * C2v + k0 + r_kg);
        Bs[(r_kg + 0) * SSTR + r_m] = kv.x;
        Bs[(r_kg + 1) * SSTR + r_m] = kv.y;
        Bs[(r_kg + 2) * SSTR + r_m] = kv.z;
        Bs[(r_kg + 3) * SSTR + r_m] = kv.w;
        __syncthreads();
        #pragma unroll
        for (int k = 0; k < BK; k++) {
            float4 a0 = *reinterpret_cast<const float4*>(&As[k * SSTR + ty * TM]);
            float4 a1 = *reinterpret_cast<const float4*>(&As[k * SSTR + ty * TM + 4]);
            float4 b0 = *reinterpret_cast<const float4*>(&Bs[k * SSTR + tx * TN]);
            float4 b1 = *reinterpret_cast<const float4*>(&Bs[k * SSTR + tx * TN + 4]);
            float a[TM] = {a0.x, a0.y, a0.z, a0.w, a1.x, a1.y, a1.z, a1.w};
            float bb[TN] = {b0.x, b0.y, b0.z, b0.w, b1.x, b1.y, b1.z, b1.w};
            #pragma unroll
            for (int i = 0; i < TM; i++)
                #pragma unroll
                for (int j = 0; j < TN; j++)
                    acc[i][j] = fmaf(a[i], bb[j], acc[i][j]);
        }
        __syncthreads();
    }

    #pragma unroll
    for (int i = 0; i < TM; i++) {
        const size_t m = (size_t)(m0 + ty * TM + i);
        float* dst = g_att + ((size_t)b * Nn + m) * Nn + n0 + tx * TN;
        *reinterpret_cast<float4*>(dst)     = make_float4(acc[i][0], acc[i][1], acc[i][2], acc[i][3]);
        *reinterpret_cast<float4*>(dst + 4) = make_float4(acc[i][4], acc[i][5], acc[i][6], acc[i][7]);
    }
}

// ---------------------------------------------------------------------------
// Kernel 3: row softmax over g_att rows (length 4096). One block per row.
// Row values held in registers (16/thread); FFMA-poly exp (no MUFU storm).
// ---------------------------------------------------------------------------
__global__ __launch_bounds__(256) void softmax_kernel()
{
    const size_t row = blockIdx.x;                // 0 .. B*N-1
    float* p = g_att + row * (size_t)Nn;
    const int t = threadIdx.x;

    float v[16];
    float mx = -1e30f;
    #pragma unroll
    for (int i = 0; i < 16; i++) {
        v[i] = p[t + i * 256];
        mx = fmaxf(mx, v[i]);
    }
    #pragma unroll
    for (int o = 16; o; o >>= 1) mx = fmaxf(mx, __shfl_xor_sync(0xffffffffu, mx, o));

    __shared__ float red[8];
    __shared__ float bmax, binv;
    if ((t & 31) == 0) red[t >> 5] = mx;
    __syncthreads();
    if (t == 0) {
        float m2 = red[0];
        #pragma unroll
        for (int w = 1; w < 8; w++) m2 = fmaxf(m2, red[w]);
        bmax = m2;
    }
    __syncthreads();
    mx = bmax;

    float s = 0.0f;
    #pragma unroll
    for (int i = 0; i < 16; i++) { v[i] = fexp(v[i] - mx); s += v[i]; }
    #pragma unroll
    for (int o = 16; o; o >>= 1) s += __shfl_xor_sync(0xffffffffu, s, o);
    if ((t & 31) == 0) red[t >> 5] = s;
    __syncthreads();
    if (t == 0) {
        float s2 = 0.0f;
        #pragma unroll
        for (int w = 0; w < 8; w++) s2 += red[w];
        binv = 1.0f / s2;
    }
    __syncthreads();
    const float inv = binv;
    #pragma unroll
    for (int i = 0; i < 16; i++) p[t + i * 256] = v[i] * inv;
}

// ---------------------------------------------------------------------------
// Kernel 4: out[b,c,m] = gamma * (sum_n A[b,m,n] vT[b,n,c]) * mask*skin + x
// Computed as outT tile [c rows x m cols] so final stores are m-contiguous.
// M=Cc=256 (c), N=4096 (m), K=4096 (n). grid (2, 32, B).
// ---------------------------------------------------------------------------
__global__ __launch_bounds__(256) void av_kernel(
    const float* __restrict__ x, const float* __restrict__ mask,
    const float* __restrict__ skin, const float* __restrict__ gamma,
    float* __restrict__ out)
{
    __shared__ float As[BK * SSTR];
    __shared__ float Bs[BK * SSTR];

    const int b  = blockIdx.z;
    const int c0 = blockIdx.x * BM;
    const int m0 = blockIdx.y * BN;
    const int tid = threadIdx.x;
    const int tx = tid & 15, ty = tid >> 4;

    const float* Vb = g_v + (size_t)b * Nn * Cc;
    const float* Ab = g_att + (size_t)b * Nn * Nn;

    const int va_n = tid >> 5;           // 0..7
    const int va_c = (tid & 31) * 4;     // 0..124
    const int bt_m = tid >> 1;           // 0..127
    const int bt_ng = (tid & 1) * 4;     // 0 or 4

    float acc[TM][TN] = {};

    for (int k0 = 0; k0 < Nn; k0 += BK) {
        // As[n][c] = vT[k0+n][c0+c]  (direct)
        float4 av = *reinterpret_cast<const float4*>(
            Vb + (size_t)(k0 + va_n) * Cc + c0 + va_c);
        *reinterpret_cast<float4*>(&As[va_n * SSTR + va_c]) = av;
        // Bs[n][m] = att[m0+m][k0+n]  (transposed)
        float4 tv = *reinterpret_cast<const float4*>(
            Ab + (size_t)(m0 + bt_m) * Nn + k0 + bt_ng);
        Bs[(bt_ng + 0) * SSTR + bt_m] = tv.x;
        Bs[(bt_ng + 1) * SSTR + bt_m] = tv.y;
        Bs[(bt_ng + 2) * SSTR + bt_m] = tv.z;
        Bs[(bt_ng + 3) * SSTR + bt_m] = tv.w;
        __syncthreads();
        #pragma unroll
        for (int k = 0; k < BK; k++) {
            float4 a0 = *reinterpret_cast<const float4*>(&As[k * SSTR + ty * TM]);
            float4 a1 = *reinterpret_cast<const float4*>(&As[k * SSTR + ty * TM + 4]);
            float4 b0 = *reinterpret_cast<const float4*>(&Bs[k * SSTR + tx * TN]);
            float4 b1 = *reinterpret_cast<const float4*>(&Bs[k * SSTR + tx * TN + 4]);
            float a[TM] = {a0.x, a0.y, a0.z, a0.w, a1.x, a1.y, a1.z, a1.w};
            float bb[TN] = {b0.x, b0.y, b0.z, b0.w, b1.x, b1.y, b1.z, b1.w};
            #pragma unroll
            for (int i = 0; i < TM; i++)
                #pragma unroll
                for (int j = 0; j < TN; j++)
                    acc[i][j] = fmaf(a[i], bb[j], acc[i][j]);
        }
        __syncthreads();
    }

    const float g = *gamma;
    const int mb = m0 + tx * TN;
    float fm[TN];
    {
        float4 mk0 = *reinterpret_cast<const float4*>(mask + (size_t)b * Nn + mb);
        float4 mk1 = *reinterpret_cast<const float4*>(mask + (size_t)b * Nn + mb + 4);
        float4 sk0 = *reinterpret_cast<const float4*>(skin + (size_t)b * Nn + mb);
        float4 sk1 = *reinterpret_cast<const float4*>(skin + (size_t)b * Nn + mb + 4);
        fm[0] = mk0.x * sk0.x; fm[1] = mk0.y * sk0.y;
        fm[2] = mk0.z * sk0.z; fm[3] = mk0.w * sk0.w;
        fm[4] = mk1.x * sk1.x; fm[5] = mk1.y * sk1.y;
        fm[6] = mk1.z * sk1.z; fm[7] = mk1.w * sk1.w;
    }

    #pragma unroll
    for (int i = 0; i < TM; i++) {
        const int c = c0 + ty * TM + i;
        const size_t base = (size_t)b * Cc * Nn + (size_t)c * Nn + mb;
        float4 x0 = *reinterpret_cast<const float4*>(x + base);
        float4 x1 = *reinterpret_cast<const float4*>(x + base + 4);
        float4 r0, r1;
        r0.x = fmaf(g, acc[i][0] * fm[0], x0.x);
        r0.y = fmaf(g, acc[i][1] * fm[1], x0.y);
        r0.z = fmaf(g, acc[i][2] * fm[2], x0.z);
        r0.w = fmaf(g, acc[i][3] * fm[3], x0.w);
        r1.x = fmaf(g, acc[i][4] * fm[4], x1.x);
        r1.y = fmaf(g, acc[i][5] * fm[5], x1.y);
        r1.z = fmaf(g, acc[i][6] * fm[6], x1.z);
        r1.w = fmaf(g, acc[i][7] * fm[7], x1.w);
        *reinterpret_cast<float4*>(out + base)     = r0;
        *reinterpret_cast<float4*>(out + base + 4) = r1;
    }
}

// ---------------------------------------------------------------------------
extern "C" void kernel_launch(void* const* d_in, const int* in_sizes, int n_in,
                              void* d_out, int out_size)
{
    (void)in_sizes; (void)n_in; (void)out_size;
    const float* x     = (const float*)d_in[0];
    const float* mask  = (const float*)d_in[1];
    const float* skin  = (const float*)d_in[2];
    const float* Wq    = (const float*)d_in[3];
    const float* bq    = (const float*)d_in[4];
    const float* Wk    = (const float*)d_in[5];
    const float* bk    = (const float*)d_in[6];
    const float* Wv    = (const float*)d_in[7];
    const float* bv    = (const float*)d_in[8];
    const float* gamma = (const float*)d_in[9];
    float* out = (float*)d_out;

    dim3 gA(4, 32, Bb);
    proj_kernel<<<gA, 256>>>(x, mask, skin, Wq, bq, Wk, bk, Wv, bv);

    dim3 gB(32, 32, Bb);
    score_kernel<<<gB, 256>>>();

    softmax_kernel<<<Bb * Nn, 256>>>();

    dim3 gD(2, 32, Bb);
    av_kernel<<<gD, 256>>>(x, mask, skin, gamma, out);
}

// round 5
// speedup vs baseline: 3.0123x; 3.0039x over previous
#include <cuda_runtime.h>
#include <cuda_fp16.h>
#include <cstdint>

// Problem constants
#define Bb 4
#define Cc 256
#define C2v 128
#define Nn 4096

// ---------------------------------------------------------------------------
// Scratch (__device__ globals; allocation-free rule)
// ---------------------------------------------------------------------------
__device__ __half g_qc[(size_t)Bb * Nn * 384];   // [B][n][384] = [qh|ql|qh]
__device__ __half g_kc[(size_t)Bb * Nn * 384];   // [B][n][384] = [kh|kh|kl] (masked)
__device__ __half g_vb[(size_t)Bb * Cc * Nn];    // [B][c][n]  (K-major for AV)
__device__ float  g_att[(size_t)Bb * Nn * Nn];   // energy fp32
__device__ __half g_attb[(size_t)Bb * Nn * Nn];  // attention fp16

// ---------------------------------------------------------------------------
// Helpers
// ---------------------------------------------------------------------------
__device__ __forceinline__ uint32_t smem_u32(const void* p) {
    uint32_t a;
    asm("{ .reg .u64 t; cvta.to.shared.u64 t, %1; cvt.u32.u64 %0, t; }" : "=r"(a) : "l"(p));
    return a;
}
__device__ __forceinline__ void cp_async16(uint32_t dst, const void* src) {
    asm volatile("cp.async.cg.shared.global [%0], [%1], 16;" :: "r"(dst), "l"(src));
}
#define CP_COMMIT() asm volatile("cp.async.commit_group;" ::: "memory")
template <int N>
__device__ __forceinline__ void cp_wait() {
    asm volatile("cp.async.wait_group %0;" :: "n"(N) : "memory");
}
__device__ __forceinline__ void ldmx4(uint32_t* r, uint32_t addr) {
    asm volatile("ldmatrix.sync.aligned.m8n8.x4.shared.b16 {%0,%1,%2,%3}, [%4];"
        : "=r"(r[0]), "=r"(r[1]), "=r"(r[2]), "=r"(r[3]) : "r"(addr));
}
__device__ __forceinline__ void mma16816(float* d, const uint32_t* a, uint32_t b0, uint32_t b1) {
    asm volatile(
        "mma.sync.aligned.m16n8k16.row.col.f32.f16.f16.f32 "
        "{%0,%1,%2,%3},{%4,%5,%6,%7},{%8,%9},{%0,%1,%2,%3};"
        : "+f"(d[0]), "+f"(d[1]), "+f"(d[2]), "+f"(d[3])
        : "r"(a[0]), "r"(a[1]), "r"(a[2]), "r"(a[3]), "r"(b0), "r"(b1));
}

// Fast exp (FFMA-only)
__device__ __forceinline__ float fexp(float x) {
    float t = fmaxf(x * 1.4426950408889634f, -126.0f);
    float fi = floorf(t);
    float f = t - fi;
    float p = 0.0013333558f;
    p = fmaf(p, f, 0.0096181291f);
    p = fmaf(p, f, 0.0555041087f);
    p = fmaf(p, f, 0.2402265069f);
    p = fmaf(p, f, 0.6931471806f);
    p = fmaf(p, f, 1.0f);
    return p * __int_as_float(((int)fi + 127) << 23);
}

// ---------------------------------------------------------------------------
// GEMM tile geometry (both MMA kernels): 128x128 block, BK=32, 8 warps (2x4)
// smem tile: 128 rows x 32 fp16, row stride 40 halves (80B)
// ---------------------------------------------------------------------------
#define ROWB 80               // bytes per smem tile row
#define STAGE_B (128 * ROWB)  // 10240 bytes per tile stage

// Load one 128x32 fp16 tile (row-major src, stride elems) into smem stage.
__device__ __forceinline__ void load_tile(uint32_t dst, const __half* src,
                                          size_t stride, int tid)
{
    #pragma unroll
    for (int i = 0; i < 2; i++) {
        int idx = tid + i * 256;          // 0..511
        int row = idx >> 2, c16 = idx & 3;
        cp_async16(dst + row * ROWB + c16 * 16, src + (size_t)row * stride + c16 * 8);
    }
}

// One BK=32 compute step for a warp: acc[4][4][4] += A(64x32) * B(32x32)^T
// A tile rows = GEMM M, B tile rows = GEMM N; both [row][k] in smem.
__device__ __forceinline__ void warp_mma_step(float acc[4][4][4], uint32_t abase,
                                              uint32_t bbase, int wy, int wx, int lane)
{
    #pragma unroll
    for (int ks = 0; ks < 2; ks++) {
        uint32_t a[4][4];
        #pragma unroll
        for (int mf = 0; mf < 4; mf++) {
            int row = wy * 64 + mf * 16 + (lane & 15);
            ldmx4(a[mf], abase + row * ROWB + ks * 32 + ((lane >> 4) << 4));
        }
        // B fragments: NON-trans ldmatrix on [n][k] tile.
        // matrix0 = n0-7/k0-7, matrix1 = n0-7/k8-15, matrix2 = n8-15/k0-7, matrix3 = n8-15/k8-15
        uint32_t bf[2][4];
        #pragma unroll
        for (int np = 0; np < 2; np++) {
            int row = wx * 32 + np * 16 + (lane & 7) + ((lane >> 4) << 3);
            ldmx4(bf[np], bbase + row * ROWB + ks * 32 + (((lane >> 3) & 1) << 4));
        }
        #pragma unroll
        for (int mf = 0; mf < 4; mf++)
            #pragma unroll
            for (int nf = 0; nf < 4; nf++)
                mma16816(acc[mf][nf], a[mf],
                         bf[nf >> 1][(nf & 1) * 2], bf[nf >> 1][(nf & 1) * 2 + 1]);
    }
}

// ---------------------------------------------------------------------------
// Kernel 1: projections (SIMT fp32) -> fp16 operands
// ---------------------------------------------------------------------------
#define BK 8
#define SSTR 132

__global__ __launch_bounds__(256) void proj_kernel(
    const float* __restrict__ x, const float* __restrict__ mask,
    const float* __restrict__ skin,
    const float* __restrict__ Wq, const float* __restrict__ bq,
    const float* __restrict__ Wk, const float* __restrict__ bk,
    const float* __restrict__ Wv, const float* __restrict__ bv)
{
    __shared__ float As[BK * SSTR];
    __shared__ float Bs[BK * SSTR];

    const int b    = blockIdx.z;
    const int m0   = blockIdx.y * 128;
    const int oblk = blockIdx.x;   // 0:q, 1:k, 2,3:v

    const float* Wp; const float* biasp; int orow0;
    if (oblk == 0)      { Wp = Wq; biasp = bq; orow0 = 0; }
    else if (oblk == 1) { Wp = Wk; biasp = bk; orow0 = 0; }
    else                { Wp = Wv; biasp = bv; orow0 = (oblk - 2) * 128; }

    const int tid = threadIdx.x;
    const int tx = tid & 15, ty = tid >> 4;
    const float* xb = x + (size_t)b * Cc * Nn;

    const int a_k = tid >> 5;
    const int a_m = (tid & 31) * 4;
    const int b_o = tid >> 1;
    const int b_kg = (tid & 1) * 4;

    float acc[8][8] = {};

    for (int k0 = 0; k0 < Cc; k0 += BK) {
        float4 av = *reinterpret_cast<const float4*>(xb + (size_t)(k0 + a_k) * Nn + m0 + a_m);
        *reinterpret_cast<float4*>(&As[a_k * SSTR + a_m]) = av;
        float4 wv = *reinterpret_cast<const float4*>(Wp + (size_t)(orow0 + b_o) * Cc + k0 + b_kg);
        Bs[(b_kg + 0) * SSTR + b_o] = wv.x;
        Bs[(b_kg + 1) * SSTR + b_o] = wv.y;
        Bs[(b_kg + 2) * SSTR + b_o] = wv.z;
        Bs[(b_kg + 3) * SSTR + b_o] = wv.w;
        __syncthreads();
        #pragma unroll
        for (int k = 0; k < BK; k++) {
            float4 a0 = *reinterpret_cast<const float4*>(&As[k * SSTR + ty * 8]);
            float4 a1 = *reinterpret_cast<const float4*>(&As[k * SSTR + ty * 8 + 4]);
            float4 b0 = *reinterpret_cast<const float4*>(&Bs[k * SSTR + tx * 8]);
            float4 b1 = *reinterpret_cast<const float4*>(&Bs[k * SSTR + tx * 8 + 4]);
            float a[8] = {a0.x, a0.y, a0.z, a0.w, a1.x, a1.y, a1.z, a1.w};
            float bb[8] = {b0.x, b0.y, b0.z, b0.w, b1.x, b1.y, b1.z, b1.w};
            #pragma unroll
            for (int i = 0; i < 8; i++)
                #pragma unroll
                for (int j = 0; j < 8; j++)
                    acc[i][j] = fmaf(a[i], bb[j], acc[i][j]);
        }
        __syncthreads();
    }

    const int obase = tx * 8;
    float bias[8];
    #pragma unroll
    for (int j = 0; j < 8; j++) bias[j] = biasp[orow0 + obase + j];

    if (oblk <= 1) {
        #pragma unroll
        for (int i = 0; i < 8; i++) {
            const int m = m0 + ty * 8 + i;
            float f = 1.0f;
            if (oblk == 1) f = (1.0f - mask[b * Nn + m]) * skin[b * Nn + m];
            __half h8[8], l8[8];
            #pragma unroll
            for (int j = 0; j < 8; j++) {
                float r = (acc[i][j] + bias[j]) * f;
                __half h = __float2half(r);
                h8[j] = h;
                l8[j] = __float2half(r - __half2float(h));
            }
            const size_t off = ((size_t)b * Nn + m) * 384 + obase;
            if (oblk == 0) {
                // qc = [qh | ql | qh]
                *reinterpret_cast<float4*>(g_qc + off)       = *reinterpret_cast<float4*>(h8);
                *reinterpret_cast<float4*>(g_qc + off + 128) = *reinterpret_cast<float4*>(l8);
                *reinterpret_cast<float4*>(g_qc + off + 256) = *reinterpret_cast<float4*>(h8);
            } else {
                // kc = [kh | kh | kl]
                *reinterpret_cast<float4*>(g_kc + off)       = *reinterpret_cast<float4*>(h8);
                *reinterpret_cast<float4*>(g_kc + off + 128) = *reinterpret_cast<float4*>(h8);
                *reinterpret_cast<float4*>(g_kc + off + 256) = *reinterpret_cast<float4*>(l8);
            }
        }
    } else {
        // v: [c][n] layout, 8 consecutive n per store
        #pragma unroll
        for (int j = 0; j < 8; j++) {
            const int c = orow0 + obase + j;
            __half h8[8];
            #pragma unroll
            for (int i = 0; i < 8; i++) h8[i] = __float2half(acc[i][j] + bias[j]);
            const size_t off = ((size_t)b * Cc + c) * Nn + m0 + ty * 8;
            *reinterpret_cast<float4*>(g_vb + off) = *reinterpret_cast<float4*>(h8);
        }
    }
}

// ---------------------------------------------------------------------------
// Kernel 2: QK^T energy via mma.sync fp16, K=384 split-fp16 concatenation
//   S = qh·kh + ql·kh + qh·kl  (fp32-class accuracy)
// grid (32 ntile, 32 mtile, B), 256 threads
// ---------------------------------------------------------------------------
__global__ __launch_bounds__(256) void qk_kernel()
{
    __shared__ __align__(128) char sm[4 * STAGE_B];
    const int b = blockIdx.z, m0 = blockIdx.y * 128, n0 = blockIdx.x * 128;
    const int tid = threadIdx.x, wid = tid >> 5, lane = tid & 31;
    const int wy = wid >> 2, wx = wid & 3;
    const uint32_t sb = smem_u32(sm);
    const uint32_t A0 = sb, A1 = sb + STAGE_B, B0 = sb + 2 * STAGE_B, B1 = sb + 3 * STAGE_B;

    const __half* Asrc = g_qc + ((size_t)b * Nn + m0) * 384;
    const __half* Bsrc = g_kc + ((size_t)b * Nn + n0) * 384;

    load_tile(A0, Asrc, 384, tid); load_tile(B0, Bsrc, 384, tid); CP_COMMIT();
    load_tile(A1, Asrc + 32, 384, tid); load_tile(B1, Bsrc + 32, 384, tid); CP_COMMIT();

    float acc[4][4][4] = {};
    const int NK = 384 / 32;
    #pragma unroll 1
    for (int ks = 0; ks < NK; ks++) {
        if (ks < NK - 1) cp_wait<1>(); else cp_wait<0>();
        __syncthreads();
        const uint32_t ab = (ks & 1) ? A1 : A0;
        const uint32_t bb = (ks & 1) ? B1 : B0;
        warp_mma_step(acc, ab, bb, wy, wx, lane);
        __syncthreads();
        if (ks + 2 < NK) {
            load_tile(ab, Asrc + (ks + 2) * 32, 384, tid);
            load_tile(bb, Bsrc + (ks + 2) * 32, 384, tid);
            CP_COMMIT();
        }
    }

    // Epilogue: fp32 energy, float2 stores
    #pragma unroll
    for (int mf = 0; mf < 4; mf++) {
        const int m = m0 + wy * 64 + mf * 16 + (lane >> 2);
        #pragma unroll
        for (int nf = 0; nf < 4; nf++) {
            const int n = n0 + wx * 32 + nf * 8 + (lane & 3) * 2;
            float* p0 = g_att + ((size_t)b * Nn + m) * Nn + n;
            float* p1 = g_att + ((size_t)b * Nn + m + 8) * Nn + n;
            *reinterpret_cast<float2*>(p0) = make_float2(acc[mf][nf][0], acc[mf][nf][1]);
            *reinterpret_cast<float2*>(p1) = make_float2(acc[mf][nf][2], acc[mf][nf][3]);
        }
    }
}

// ---------------------------------------------------------------------------
// Kernel 3: row softmax (fp32 in -> fp16 out)
// ---------------------------------------------------------------------------
__global__ __launch_bounds__(256) void softmax_kernel()
{
    const size_t row = blockIdx.x;
    const float* p = g_att + row * (size_t)Nn;
    __half* pb = g_attb + row * (size_t)Nn;
    const int t = threadIdx.x;

    float v[16];
    {
        const float4* pr = reinterpret_cast<const float4*>(p + t * 16);
        float4 a0 = pr[0], a1 = pr[1], a2 = pr[2], a3 = pr[3];
        v[0]=a0.x; v[1]=a0.y; v[2]=a0.z; v[3]=a0.w;
        v[4]=a1.x; v[5]=a1.y; v[6]=a1.z; v[7]=a1.w;
        v[8]=a2.x; v[9]=a2.y; v[10]=a2.z; v[11]=a2.w;
        v[12]=a3.x; v[13]=a3.y; v[14]=a3.z; v[15]=a3.w;
    }
    float mx = v[0];
    #pragma unroll
    for (int i = 1; i < 16; i++) mx = fmaxf(mx, v[i]);
    #pragma unroll
    for (int o = 16; o; o >>= 1) mx = fmaxf(mx, __shfl_xor_sync(0xffffffffu, mx, o));

    __shared__ float red[8];
    __shared__ float bmax, binv;
    if ((t & 31) == 0) red[t >> 5] = mx;
    __syncthreads();
    if (t == 0) {
        float m2 = red[0];
        #pragma unroll
        for (int w = 1; w < 8; w++) m2 = fmaxf(m2, red[w]);
        bmax = m2;
    }
    __syncthreads();
    mx = bmax;

    float s = 0.0f;
    #pragma unroll
    for (int i = 0; i < 16; i++) { v[i] = fexp(v[i] - mx); s += v[i]; }
    #pragma unroll
    for (int o = 16; o; o >>= 1) s += __shfl_xor_sync(0xffffffffu, s, o);
    if ((t & 31) == 0) red[t >> 5] = s;
    __syncthreads();
    if (t == 0) {
        float s2 = 0.0f;
        #pragma unroll
        for (int w = 0; w < 8; w++) s2 += red[w];
        binv = 1.0f / s2;
    }
    __syncthreads();
    const float inv = binv;

    __half h[16];
    #pragma unroll
    for (int i = 0; i < 16; i++) h[i] = __float2half(v[i] * inv);
    float4* po = reinterpret_cast<float4*>(pb + t * 16);
    po[0] = reinterpret_cast<float4*>(h)[0];
    po[1] = reinterpret_cast<float4*>(h)[1];
}

// ---------------------------------------------------------------------------
// Kernel 4: AV via mma.sync fp16 + fused epilogue
//   D[m][c] = sum_n att[m][n] * v[c][n];  out[b][c][m] = g*D*fm[m] + x[b][c][m]
// grid (2 ctile, 32 mtile, B), 256 threads
// ---------------------------------------------------------------------------
__global__ __launch_bounds__(256) void av_kernel(
    const float* __restrict__ x, const float* __restrict__ mask,
    const float* __restrict__ skin, const float* __restrict__ gamma,
    float* __restrict__ out)
{
    __shared__ __align__(128) char sm[4 * STAGE_B];
    __shared__ float fmv[128];
    const int b = blockIdx.z, m0 = blockIdx.y * 128, c0 = blockIdx.x * 128;
    const int tid = threadIdx.x, wid = tid >> 5, lane = tid & 31;
    const int wy = wid >> 2, wx = wid & 3;
    const uint32_t sb = smem_u32(sm);
    const uint32_t A0 = sb, A1 = sb + STAGE_B, B0 = sb + 2 * STAGE_B, B1 = sb + 3 * STAGE_B;

    if (tid < 128)
        fmv[tid] = mask[(size_t)b * Nn + m0 + tid] * skin[(size_t)b * Nn + m0 + tid];

    const __half* Asrc = g_attb + ((size_t)b * Nn + m0) * Nn;
    const __half* Bsrc = g_vb + ((size_t)b * Cc + c0) * Nn;

    load_tile(A0, Asrc, Nn, tid); load_tile(B0, Bsrc, Nn, tid); CP_COMMIT();
    load_tile(A1, Asrc + 32, Nn, tid); load_tile(B1, Bsrc + 32, Nn, tid); CP_COMMIT();

    float acc[4][4][4] = {};
    const int NK = Nn / 32;   // 128
    #pragma unroll 1
    for (int ks = 0; ks < NK; ks++) {
        if (ks < NK - 1) cp_wait<1>(); else cp_wait<0>();
        __syncthreads();
        const uint32_t ab = (ks & 1) ? A1 : A0;
        const uint32_t bb = (ks & 1) ? B1 : B0;
        warp_mma_step(acc, ab, bb, wy, wx, lane);
        __syncthreads();
        if (ks + 2 < NK) {
            load_tile(ab, Asrc + (ks + 2) * 32, Nn, tid);
            load_tile(bb, Bsrc + (ks + 2) * 32, Nn, tid);
            CP_COMMIT();
        }
    }

    // Fused epilogue: out[c][m] = gamma*fm[m]*D[m][c] + x[c][m]
    const float gm = __ldg(gamma);
    #pragma unroll
    for (int mf = 0; mf < 4; mf++) {
        const int ml = wy * 64 + mf * 16 + (lane >> 2);    // local m (0..127)
        const float f0 = gm * fmv[ml];
        const float f1 = gm * fmv[ml + 8];
        #pragma unroll
        for (int nf = 0; nf < 4; nf++) {
            const int c = c0 + wx * 32 + nf * 8 + (lane & 3) * 2;
            const size_t b0i = ((size_t)b * Cc + c) * Nn + m0 + ml;
            const size_t b1i = b0i + Nn;   // c+1
            out[b0i]     = fmaf(f0, acc[mf][nf][0], x[b0i]);
            out[b1i]     = fmaf(f0, acc[mf][nf][1], x[b1i]);
            out[b0i + 8] = fmaf(f1, acc[mf][nf][2], x[b0i + 8]);
            out[b1i + 8] = fmaf(f1, acc[mf][nf][3], x[b1i + 8]);
        }
    }
}

// ---------------------------------------------------------------------------
extern "C" void kernel_launch(void* const* d_in, const int* in_sizes, int n_in,
                              void* d_out, int out_size)
{
    (void)in_sizes; (void)n_in; (void)out_size;
    const float* x     = (const float*)d_in[0];
    const float* mask  = (const float*)d_in[1];
    const float* skin  = (const float*)d_in[2];
    const float* Wq    = (const float*)d_in[3];
    const float* bq    = (const float*)d_in[4];
    const float* Wk    = (const float*)d_in[5];
    const float* bk    = (const float*)d_in[6];
    const float* Wv    = (const float*)d_in[7];
    const float* bv    = (const float*)d_in[8];
    const float* gamma = (const float*)d_in[9];
    float* out = (float*)d_out;

    dim3 gA(4, 32, Bb);
    proj_kernel<<<gA, 256>>>(x, mask, skin, Wq, bq, Wk, bk, Wv, bv);

    dim3 gQK(32, 32, Bb);
    qk_kernel<<<gQK, 256>>>();

    softmax_kernel<<<Bb * Nn, 256>>>();

    dim3 gAV(2, 32, Bb);
    av_kernel<<<gAV, 256>>>(x, mask, skin, gamma, out);
}